// round 11
// baseline (speedup 1.0000x reference)
#include <cuda_runtime.h>
#include <cuda_bf16.h>

#define Nn   100000
#define Ee   1600000
#define F    128          // IN_F == HIDDEN
#define C2T  80           // HEADS * N_CLASSES
#define NCls 40
#define NEG  0.2f
#define EPS  1e-5f

// ---------------- scratch (static device globals; no runtime alloc) ----------
__device__ __align__(16) __nv_bfloat16 g_h1b[Nn * F];     // bf16 payload, layer 1
__device__ __align__(16) __nv_bfloat16 g_h2b[Nn * C2T];   // bf16 payload, layer 2
__device__ __align__(16) float g_out1[Nn * F];            // un-normalized accum
__device__ __align__(16) float g_out2[Nn * C2T];          // un-normalized accum

__device__ __align__(16) float g_asrc1[Nn * 2], g_adst1[Nn * 2], g_den1[Nn * 2];
__device__ __align__(16) float g_asrc2[Nn * 2], g_adst2[Nn * 2], g_den2[Nn * 2];

__device__ float g_bns[F], g_bnq[F], g_scale[F], g_shift[F];

// ---------------- helpers ----------------------------------------------------
__device__ __forceinline__ float lrelu(float x){ return x > 0.f ? x : NEG * x; }

__device__ __forceinline__ void red4(float* p, float a, float b, float c, float d) {
    asm volatile("red.global.add.v4.f32 [%0], {%1,%2,%3,%4};"
                 :: "l"(p), "f"(a), "f"(b), "f"(c), "f"(d) : "memory");
}
__device__ __forceinline__ void red2(float* p, float a, float b) {
    asm volatile("red.global.add.v2.f32 [%0], {%1,%2};"
                 :: "l"(p), "f"(a), "f"(b) : "memory");
}
__device__ __forceinline__ unsigned f2tf32(float f) {
    unsigned u;
    asm("cvt.rna.tf32.f32 %0, %1;" : "=r"(u) : "f"(f));
    return u;
}
__device__ __forceinline__ void mma_tf32(float* d, const unsigned* a, const unsigned* b) {
    asm volatile(
        "mma.sync.aligned.m16n8k8.row.col.f32.tf32.tf32.f32 "
        "{%0,%1,%2,%3}, {%4,%5,%6,%7}, {%8,%9}, {%0,%1,%2,%3};\n"
        : "+f"(d[0]), "+f"(d[1]), "+f"(d[2]), "+f"(d[3])
        : "r"(a[0]), "r"(a[1]), "r"(a[2]), "r"(a[3]), "r"(b[0]), "r"(b[1]));
}

// ================= GEMM1: h1 = x @ W1 (tf32); fused att dots + self-msg seed =
// block 256 thr = 8 warps; block tile 128x128; warp tile 32(M) x 64(N)
__global__ __launch_bounds__(256)
void k_gemm1(const float* __restrict__ x, const float* __restrict__ W,
             const float* __restrict__ attS, const float* __restrict__ attD) {
    __shared__ unsigned As[128][36];
    __shared__ unsigned Bs[32][136];
    int tid  = threadIdx.x;
    int lane = tid & 31, wid = tid >> 5;
    int warpM = wid & 3, warpN = wid >> 2;   // 4 x 2; warpN == head
    int g = lane >> 2, tig = lane & 3;
    int rowBase = blockIdx.x * 128;
    float acc[2][8][4] = {};

    if (blockIdx.x == 0 && tid < F) { g_bns[tid] = 0.f; g_bnq[tid] = 0.f; }

    for (int k0 = 0; k0 < F; k0 += 32) {
        #pragma unroll
        for (int l = 0; l < 4; l++) {               // A tile 128x32
            int v = tid + l * 256;
            int r = v >> 3, kq = v & 7;
            int grow = rowBase + r;
            float4 xv = make_float4(0.f, 0.f, 0.f, 0.f);
            if (grow < Nn) xv = *(const float4*)&x[grow * F + k0 + kq * 4];
            As[r][kq*4+0] = f2tf32(xv.x); As[r][kq*4+1] = f2tf32(xv.y);
            As[r][kq*4+2] = f2tf32(xv.z); As[r][kq*4+3] = f2tf32(xv.w);
        }
        #pragma unroll
        for (int l = 0; l < 4; l++) {               // B tile 32x128
            int v = tid + l * 256;
            int kk = v >> 5, nq = v & 31;
            float4 wv = *(const float4*)&W[(k0 + kk) * F + nq * 4];
            Bs[kk][nq*4+0] = f2tf32(wv.x); Bs[kk][nq*4+1] = f2tf32(wv.y);
            Bs[kk][nq*4+2] = f2tf32(wv.z); Bs[kk][nq*4+3] = f2tf32(wv.w);
        }
        __syncthreads();
        #pragma unroll
        for (int ks = 0; ks < 4; ks++) {
            unsigned a[2][4];
            #pragma unroll
            for (int mi = 0; mi < 2; mi++) {
                int r = warpM * 32 + mi * 16 + g;
                a[mi][0] = As[r    ][ks*8 + tig];
                a[mi][1] = As[r + 8][ks*8 + tig];
                a[mi][2] = As[r    ][ks*8 + tig + 4];
                a[mi][3] = As[r + 8][ks*8 + tig + 4];
            }
            #pragma unroll
            for (int ni = 0; ni < 8; ni++) {
                unsigned b[2];
                int c = warpN * 64 + ni * 8 + g;
                b[0] = Bs[ks*8 + tig    ][c];
                b[1] = Bs[ks*8 + tig + 4][c];
                mma_tf32(acc[0][ni], a[0], b);
                mma_tf32(acc[1][ni], a[1], b);
            }
        }
        __syncthreads();
    }

    // epilogue: att dots -> e_self; store h1(bf16), out1 seed = e_self*h1,
    // asrc/adst/den (non-atomic)
    #pragma unroll
    for (int mi = 0; mi < 2; mi++) {
        int r0 = rowBase + warpM * 32 + mi * 16 + g;
        int r1 = r0 + 8;
        float as0 = 0.f, ad0 = 0.f, as1 = 0.f, ad1 = 0.f;
        #pragma unroll
        for (int ni = 0; ni < 8; ni++) {
            int c0 = warpN * 64 + ni * 8 + 2 * tig;
            float sa = __ldg(&attS[c0]), sb = __ldg(&attS[c0 + 1]);
            float da = __ldg(&attD[c0]), db = __ldg(&attD[c0 + 1]);
            as0 += acc[mi][ni][0] * sa + acc[mi][ni][1] * sb;
            ad0 += acc[mi][ni][0] * da + acc[mi][ni][1] * db;
            as1 += acc[mi][ni][2] * sa + acc[mi][ni][3] * sb;
            ad1 += acc[mi][ni][2] * da + acc[mi][ni][3] * db;
        }
        as0 += __shfl_xor_sync(0xffffffff, as0, 1); as0 += __shfl_xor_sync(0xffffffff, as0, 2);
        ad0 += __shfl_xor_sync(0xffffffff, ad0, 1); ad0 += __shfl_xor_sync(0xffffffff, ad0, 2);
        as1 += __shfl_xor_sync(0xffffffff, as1, 1); as1 += __shfl_xor_sync(0xffffffff, as1, 2);
        ad1 += __shfl_xor_sync(0xffffffff, ad1, 1); ad1 += __shfl_xor_sync(0xffffffff, ad1, 2);
        float e0 = __expf(lrelu(as0 + ad0));
        float e1 = __expf(lrelu(as1 + ad1));
        #pragma unroll
        for (int ni = 0; ni < 8; ni++) {
            int c0 = warpN * 64 + ni * 8 + 2 * tig;
            if (r0 < Nn) {
                *(__nv_bfloat162*)&g_h1b[r0 * F + c0] =
                    __float22bfloat162_rn(make_float2(acc[mi][ni][0], acc[mi][ni][1]));
                *(float2*)&g_out1[r0 * F + c0] =
                    make_float2(e0 * acc[mi][ni][0], e0 * acc[mi][ni][1]);
            }
            if (r1 < Nn) {
                *(__nv_bfloat162*)&g_h1b[r1 * F + c0] =
                    __float22bfloat162_rn(make_float2(acc[mi][ni][2], acc[mi][ni][3]));
                *(float2*)&g_out1[r1 * F + c0] =
                    make_float2(e1 * acc[mi][ni][2], e1 * acc[mi][ni][3]);
            }
        }
        if (tig == 0) {
            if (r0 < Nn) { g_asrc1[r0*2+warpN] = as0; g_adst1[r0*2+warpN] = ad0; g_den1[r0*2+warpN] = e0; }
            if (r1 < Nn) { g_asrc1[r1*2+warpN] = as1; g_adst1[r1*2+warpN] = ad1; g_den1[r1*2+warpN] = e1; }
        }
    }
}

// ======= msg1: warp/edge; un-normalized scatter + den accumulation ===========
__global__ __launch_bounds__(256)
void k_msg1(const int* __restrict__ src, const int* __restrict__ dst) {
    int warp = (blockIdx.x * blockDim.x + threadIdx.x) >> 5;
    int lane = threadIdx.x & 31;
    if (warp >= Ee) return;
    int s = __ldg(&src[warp]);
    int d = __ldg(&dst[warp]);
    float e0 = 0.f, e1 = 0.f;
    if (lane == 0) {
        float2 a = *(const float2*)&g_asrc1[s * 2];
        float2 b = *(const float2*)&g_adst1[d * 2];
        e0 = __expf(lrelu(a.x + b.x));
        e1 = __expf(lrelu(a.y + b.y));
        red2(&g_den1[d * 2], e0, e1);
    }
    e0 = __shfl_sync(0xffffffff, e0, 0);
    e1 = __shfl_sync(0xffffffff, e1, 0);
    float w = (lane >= 16) ? e1 : e0;

    uint2 p = *(const uint2*)((const char*)g_h1b + (size_t)s * 256 + lane * 8);
    float2 f0 = __bfloat1622float2(*(__nv_bfloat162*)&p.x);
    float2 f1 = __bfloat1622float2(*(__nv_bfloat162*)&p.y);
    red4(&g_out1[d * F + lane * 4], f0.x * w, f0.y * w, f1.x * w, f1.y * w);
}

// ----- BN stats over normalized out1; also den1 -> 1/den1 (fused rinv) -------
// Each block owns rows [i0, i0+64); it inverts its own den entries (disjoint
// across blocks, race-free) and caches them in smem for the stats loop.
__global__ __launch_bounds__(128)
void k_stats() {
    __shared__ float sinv[128];             // 64 rows x 2 heads
    int c = threadIdx.x;                    // 128 threads, one per feature
    int i0 = blockIdx.x * 64;
    int head = c >> 6;
    int t = i0 * 2 + c;                     // den index covered by this thread
    if (t < 2 * Nn) {
        float inv = 1.0f / g_den1[t];
        g_den1[t] = inv;                    // write back for GEMM2's A-load
        sinv[c] = inv;
    }
    __syncthreads();
    float s = 0.f, q = 0.f;
    for (int r = 0; r < 64; r++) {
        int i = i0 + r;
        if (i >= Nn) break;
        float v = g_out1[i * F + c] * sinv[r * 2 + head];
        s += v; q += v * v;
    }
    atomicAdd(&g_bns[c], s);
    atomicAdd(&g_bnq[c], q);
}

__global__ void k_bnf(const float* __restrict__ gamma, const float* __restrict__ beta) {
    int c = threadIdx.x;
    float m = g_bns[c] / (float)Nn;
    float v = g_bnq[c] / (float)Nn - m * m;
    float sc = gamma[c] * rsqrtf(v + EPS);
    g_scale[c] = sc;
    g_shift[c] = beta[c] - m * sc;
}

// ================= GEMM2: h2 = BN(out1*invden) @ W2 (tf32) ===================
// block tile 128x80; warp tile 32(M) x 40(N); warpN == head
__global__ __launch_bounds__(256)
void k_gemm2(const float* __restrict__ W, const float* __restrict__ attS,
             const float* __restrict__ attD) {
    __shared__ unsigned As[128][36];
    __shared__ unsigned Bs[32][88];
    __shared__ float sc[F], sh[F];
    int tid  = threadIdx.x;
    int lane = tid & 31, wid = tid >> 5;
    int warpM = wid & 3, warpN = wid >> 2;
    int g = lane >> 2, tig = lane & 3;
    int rowBase = blockIdx.x * 128;
    float acc[2][5][4] = {};

    if (tid < F) { sc[tid] = g_scale[tid]; sh[tid] = g_shift[tid]; }
    __syncthreads();

    for (int k0 = 0; k0 < F; k0 += 32) {
        #pragma unroll
        for (int l = 0; l < 4; l++) {               // A tile: normalize + BN at load
            int v = tid + l * 256;
            int r = v >> 3, kq = v & 7;
            int grow = rowBase + r;
            int kc = k0 + kq * 4;
            float4 xv = make_float4(0.f, 0.f, 0.f, 0.f);
            float inv = 0.f;
            if (grow < Nn) {
                xv  = *(const float4*)&g_out1[grow * F + kc];
                inv = g_den1[grow * 2 + (kc >= 64)];
            }
            As[r][kq*4+0] = f2tf32(xv.x * inv * sc[kc+0] + sh[kc+0]);
            As[r][kq*4+1] = f2tf32(xv.y * inv * sc[kc+1] + sh[kc+1]);
            As[r][kq*4+2] = f2tf32(xv.z * inv * sc[kc+2] + sh[kc+2]);
            As[r][kq*4+3] = f2tf32(xv.w * inv * sc[kc+3] + sh[kc+3]);
        }
        #pragma unroll
        for (int l = 0; l < 3; l++) {               // B tile 32x80 = 640 float4
            int v = tid + l * 256;
            if (v < 640) {
                int kk = v / 20, nq = v % 20;
                float4 wv = *(const float4*)&W[(k0 + kk) * C2T + nq * 4];
                Bs[kk][nq*4+0] = f2tf32(wv.x); Bs[kk][nq*4+1] = f2tf32(wv.y);
                Bs[kk][nq*4+2] = f2tf32(wv.z); Bs[kk][nq*4+3] = f2tf32(wv.w);
            }
        }
        __syncthreads();
        #pragma unroll
        for (int ks = 0; ks < 4; ks++) {
            unsigned a[2][4];
            #pragma unroll
            for (int mi = 0; mi < 2; mi++) {
                int r = warpM * 32 + mi * 16 + g;
                a[mi][0] = As[r    ][ks*8 + tig];
                a[mi][1] = As[r + 8][ks*8 + tig];
                a[mi][2] = As[r    ][ks*8 + tig + 4];
                a[mi][3] = As[r + 8][ks*8 + tig + 4];
            }
            #pragma unroll
            for (int ni = 0; ni < 5; ni++) {
                unsigned b[2];
                int c = warpN * 40 + ni * 8 + g;
                b[0] = Bs[ks*8 + tig    ][c];
                b[1] = Bs[ks*8 + tig + 4][c];
                mma_tf32(acc[0][ni], a[0], b);
                mma_tf32(acc[1][ni], a[1], b);
            }
        }
        __syncthreads();
    }

    #pragma unroll
    for (int mi = 0; mi < 2; mi++) {
        int r0 = rowBase + warpM * 32 + mi * 16 + g;
        int r1 = r0 + 8;
        float as0 = 0.f, ad0 = 0.f, as1 = 0.f, ad1 = 0.f;
        #pragma unroll
        for (int ni = 0; ni < 5; ni++) {
            int c0 = warpN * 40 + ni * 8 + 2 * tig;
            float sa = __ldg(&attS[c0]), sb = __ldg(&attS[c0 + 1]);
            float da = __ldg(&attD[c0]), db = __ldg(&attD[c0 + 1]);
            as0 += acc[mi][ni][0] * sa + acc[mi][ni][1] * sb;
            ad0 += acc[mi][ni][0] * da + acc[mi][ni][1] * db;
            as1 += acc[mi][ni][2] * sa + acc[mi][ni][3] * sb;
            ad1 += acc[mi][ni][2] * da + acc[mi][ni][3] * db;
        }
        as0 += __shfl_xor_sync(0xffffffff, as0, 1); as0 += __shfl_xor_sync(0xffffffff, as0, 2);
        ad0 += __shfl_xor_sync(0xffffffff, ad0, 1); ad0 += __shfl_xor_sync(0xffffffff, ad0, 2);
        as1 += __shfl_xor_sync(0xffffffff, as1, 1); as1 += __shfl_xor_sync(0xffffffff, as1, 2);
        ad1 += __shfl_xor_sync(0xffffffff, ad1, 1); ad1 += __shfl_xor_sync(0xffffffff, ad1, 2);
        float e0 = __expf(lrelu(as0 + ad0));
        float e1 = __expf(lrelu(as1 + ad1));
        #pragma unroll
        for (int ni = 0; ni < 5; ni++) {
            int c0 = warpN * 40 + ni * 8 + 2 * tig;
            if (r0 < Nn) {
                *(__nv_bfloat162*)&g_h2b[r0 * C2T + c0] =
                    __float22bfloat162_rn(make_float2(acc[mi][ni][0], acc[mi][ni][1]));
                *(float2*)&g_out2[r0 * C2T + c0] =
                    make_float2(e0 * acc[mi][ni][0], e0 * acc[mi][ni][1]);
            }
            if (r1 < Nn) {
                *(__nv_bfloat162*)&g_h2b[r1 * C2T + c0] =
                    __float22bfloat162_rn(make_float2(acc[mi][ni][2], acc[mi][ni][3]));
                *(float2*)&g_out2[r1 * C2T + c0] =
                    make_float2(e1 * acc[mi][ni][2], e1 * acc[mi][ni][3]);
            }
        }
        if (tig == 0) {
            if (r0 < Nn) { g_asrc2[r0*2+warpN] = as0; g_adst2[r0*2+warpN] = ad0; g_den2[r0*2+warpN] = e0; }
            if (r1 < Nn) { g_asrc2[r1*2+warpN] = as1; g_adst2[r1*2+warpN] = ad1; g_den2[r1*2+warpN] = e1; }
        }
    }
}

// ======= msg2: warp/edge (20 active lanes); un-normalized scatter + den ======
__global__ __launch_bounds__(256)
void k_msg2(const int* __restrict__ src, const int* __restrict__ dst) {
    int warp = (blockIdx.x * blockDim.x + threadIdx.x) >> 5;
    int lane = threadIdx.x & 31;
    if (warp >= Ee) return;
    int s = __ldg(&src[warp]);
    int d = __ldg(&dst[warp]);
    float e0 = 0.f, e1 = 0.f;
    if (lane == 0) {
        float2 a = *(const float2*)&g_asrc2[s * 2];
        float2 b = *(const float2*)&g_adst2[d * 2];
        e0 = __expf(lrelu(a.x + b.x));
        e1 = __expf(lrelu(a.y + b.y));
        red2(&g_den2[d * 2], e0, e1);
    }
    e0 = __shfl_sync(0xffffffff, e0, 0);
    e1 = __shfl_sync(0xffffffff, e1, 0);
    if (lane >= 20) return;
    int h = lane >= 10;
    int q = lane - h * 10;
    float w = h ? e1 : e0;

    uint2 p = *(const uint2*)((const char*)g_h2b + (size_t)s * 160 + h * 80 + q * 8);
    float2 f0 = __bfloat1622float2(*(__nv_bfloat162*)&p.x);
    float2 f1 = __bfloat1622float2(*(__nv_bfloat162*)&p.y);
    red4(&g_out2[d * C2T + h * 40 + q * 4], f0.x * w, f0.y * w, f1.x * w, f1.y * w);
}

// ------- final: normalize + head mean + bias + log_softmax -------------------
__global__ __launch_bounds__(256)
void k_final2(const float* __restrict__ b2, float* __restrict__ out) {
    int i = (blockIdx.x * blockDim.x + threadIdx.x) >> 5;
    int lane = threadIdx.x & 31;
    if (i >= Nn) return;
    float inv0 = 0.f, inv1 = 0.f;
    if (lane == 0) {
        float2 dn = *(const float2*)&g_den2[i * 2];
        inv0 = 0.5f / dn.x;
        inv1 = 0.5f / dn.y;
    }
    inv0 = __shfl_sync(0xffffffff, inv0, 0);
    inv1 = __shfl_sync(0xffffffff, inv1, 0);
    const float* o = &g_out2[i * C2T];

    int c = lane;                            // classes 0..31
    float va = o[c] * inv0 + o[40 + c] * inv1 + __ldg(&b2[c]);
    float vb = -1e30f;
    if (lane < 8) {
        int cb = lane + 32;
        vb = o[cb] * inv0 + o[40 + cb] * inv1 + __ldg(&b2[cb]);
    }
    float m = fmaxf(va, vb);
    #pragma unroll
    for (int off = 16; off; off >>= 1) m = fmaxf(m, __shfl_xor_sync(0xffffffff, m, off));
    float s = __expf(va - m) + (lane < 8 ? __expf(vb - m) : 0.f);
    #pragma unroll
    for (int off = 16; off; off >>= 1) s += __shfl_xor_sync(0xffffffff, s, off);
    float lg = m + __logf(s);
    out[i * NCls + lane] = va - lg;
    if (lane < 8) out[i * NCls + 32 + lane] = vb - lg;
}

// ---------------- launch -----------------------------------------------------
extern "C" void kernel_launch(void* const* d_in, const int* in_sizes, int n_in,
                              void* d_out, int out_size) {
    const float* x     = (const float*)d_in[0];
    const int*   ei    = (const int*)  d_in[1];
    const float* W1    = (const float*)d_in[2];
    const float* as1   = (const float*)d_in[3];
    const float* ad1   = (const float*)d_in[4];
    // d_in[5] = b1 (cancels inside BatchNorm — unused)
    const float* gamma = (const float*)d_in[6];
    const float* beta  = (const float*)d_in[7];
    const float* W2    = (const float*)d_in[8];
    const float* as2   = (const float*)d_in[9];
    const float* ad2   = (const float*)d_in[10];
    const float* b2    = (const float*)d_in[11];
    float* out = (float*)d_out;

    const int* src = ei;
    const int* dst = ei + Ee;

    const int TB = 256;
    int gG  = (Nn + 127) / 128;
    int gEw = (Ee * 32 + TB - 1) / TB;       // warp per edge

    // ---- layer 1 ----
    k_gemm1<<<gG, TB>>>(x, W1, as1, ad1);
    k_msg1<<<gEw, TB>>>(src, dst);
    k_stats<<<(Nn + 63) / 64, 128>>>();      // fused: rinv(den1) + BN stats
    k_bnf<<<1, 128>>>(gamma, beta);

    // ---- layer 2 ----
    k_gemm2<<<gG, TB>>>(W2, as2, ad2);
    k_msg2<<<gEw, TB>>>(src, dst);
    k_final2<<<(Nn * 32 + TB - 1) / TB, TB>>>(b2, out);
}

// round 14
// speedup vs baseline: 1.1853x; 1.1853x over previous
#include <cuda_runtime.h>
#include <cuda_bf16.h>

#define Nn   100000
#define Ee   1600000
#define F    128          // IN_F == HIDDEN
#define C2T  80           // HEADS * N_CLASSES
#define NCls 40
#define NEG  0.2f
#define EPS  1e-5f

// ---------------- scratch (static device globals; no runtime alloc) ----------
__device__ __align__(16) __nv_bfloat16 g_h1b[Nn * F];     // bf16 payload, layer 1
__device__ __align__(16) __nv_bfloat16 g_h2b[Nn * C2T];   // bf16 payload, layer 2
__device__ __align__(16) float g_out1[Nn * F];            // un-normalized accum
__device__ __align__(16) float g_out2[Nn * C2T];          // un-normalized accum

__device__ __align__(16) float g_asrc1[Nn * 2], g_adst1[Nn * 2], g_den1[Nn * 2];
__device__ __align__(16) float g_asrc2[Nn * 2], g_adst2[Nn * 2], g_den2[Nn * 2];

__device__ float g_bns[F], g_bnq[F];

// ---------------- helpers ----------------------------------------------------
__device__ __forceinline__ float lrelu(float x){ return x > 0.f ? x : NEG * x; }

__device__ __forceinline__ void red4(float* p, float a, float b, float c, float d) {
    asm volatile("red.global.add.v4.f32 [%0], {%1,%2,%3,%4};"
                 :: "l"(p), "f"(a), "f"(b), "f"(c), "f"(d) : "memory");
}
__device__ __forceinline__ void red2(float* p, float a, float b) {
    asm volatile("red.global.add.v2.f32 [%0], {%1,%2};"
                 :: "l"(p), "f"(a), "f"(b) : "memory");
}
__device__ __forceinline__ unsigned f2tf32(float f) {
    unsigned u;
    asm("cvt.rna.tf32.f32 %0, %1;" : "=r"(u) : "f"(f));
    return u;
}
__device__ __forceinline__ void mma_tf32(float* d, const unsigned* a, const unsigned* b) {
    asm volatile(
        "mma.sync.aligned.m16n8k8.row.col.f32.tf32.tf32.f32 "
        "{%0,%1,%2,%3}, {%4,%5,%6,%7}, {%8,%9}, {%0,%1,%2,%3};\n"
        : "+f"(d[0]), "+f"(d[1]), "+f"(d[2]), "+f"(d[3])
        : "r"(a[0]), "r"(a[1]), "r"(a[2]), "r"(a[3]), "r"(b[0]), "r"(b[1]));
}

template<int L> __device__ __forceinline__ float* P_asrc() { return L == 1 ? g_asrc1 : g_asrc2; }
template<int L> __device__ __forceinline__ float* P_adst() { return L == 1 ? g_adst1 : g_adst2; }
template<int L> __device__ __forceinline__ float* P_den()  { return L == 1 ? g_den1  : g_den2;  }

// ================= GEMM1: h1 = x @ W1 (tf32); fused att dots + self-msg seed =
// block 256 thr = 8 warps; block tile 128x128; warp tile 32(M) x 64(N)
__global__ __launch_bounds__(256)
void k_gemm1(const float* __restrict__ x, const float* __restrict__ W,
             const float* __restrict__ attS, const float* __restrict__ attD) {
    __shared__ unsigned As[128][36];
    __shared__ unsigned Bs[32][136];
    int tid  = threadIdx.x;
    int lane = tid & 31, wid = tid >> 5;
    int warpM = wid & 3, warpN = wid >> 2;   // 4 x 2; warpN == head
    int g = lane >> 2, tig = lane & 3;
    int rowBase = blockIdx.x * 128;
    float acc[2][8][4] = {};

    if (blockIdx.x == 0 && tid < F) { g_bns[tid] = 0.f; g_bnq[tid] = 0.f; }

    for (int k0 = 0; k0 < F; k0 += 32) {
        #pragma unroll
        for (int l = 0; l < 4; l++) {               // A tile 128x32
            int v = tid + l * 256;
            int r = v >> 3, kq = v & 7;
            int grow = rowBase + r;
            float4 xv = make_float4(0.f, 0.f, 0.f, 0.f);
            if (grow < Nn) xv = *(const float4*)&x[grow * F + k0 + kq * 4];
            As[r][kq*4+0] = f2tf32(xv.x); As[r][kq*4+1] = f2tf32(xv.y);
            As[r][kq*4+2] = f2tf32(xv.z); As[r][kq*4+3] = f2tf32(xv.w);
        }
        #pragma unroll
        for (int l = 0; l < 4; l++) {               // B tile 32x128
            int v = tid + l * 256;
            int kk = v >> 5, nq = v & 31;
            float4 wv = *(const float4*)&W[(k0 + kk) * F + nq * 4];
            Bs[kk][nq*4+0] = f2tf32(wv.x); Bs[kk][nq*4+1] = f2tf32(wv.y);
            Bs[kk][nq*4+2] = f2tf32(wv.z); Bs[kk][nq*4+3] = f2tf32(wv.w);
        }
        __syncthreads();
        #pragma unroll
        for (int ks = 0; ks < 4; ks++) {
            unsigned a[2][4];
            #pragma unroll
            for (int mi = 0; mi < 2; mi++) {
                int r = warpM * 32 + mi * 16 + g;
                a[mi][0] = As[r    ][ks*8 + tig];
                a[mi][1] = As[r + 8][ks*8 + tig];
                a[mi][2] = As[r    ][ks*8 + tig + 4];
                a[mi][3] = As[r + 8][ks*8 + tig + 4];
            }
            #pragma unroll
            for (int ni = 0; ni < 8; ni++) {
                unsigned b[2];
                int c = warpN * 64 + ni * 8 + g;
                b[0] = Bs[ks*8 + tig    ][c];
                b[1] = Bs[ks*8 + tig + 4][c];
                mma_tf32(acc[0][ni], a[0], b);
                mma_tf32(acc[1][ni], a[1], b);
            }
        }
        __syncthreads();
    }

    // epilogue: att dots -> e_self; store h1(bf16), out1 seed = e_self*h1,
    // asrc/adst/den (non-atomic)
    #pragma unroll
    for (int mi = 0; mi < 2; mi++) {
        int r0 = rowBase + warpM * 32 + mi * 16 + g;
        int r1 = r0 + 8;
        float as0 = 0.f, ad0 = 0.f, as1 = 0.f, ad1 = 0.f;
        #pragma unroll
        for (int ni = 0; ni < 8; ni++) {
            int c0 = warpN * 64 + ni * 8 + 2 * tig;
            float sa = __ldg(&attS[c0]), sb = __ldg(&attS[c0 + 1]);
            float da = __ldg(&attD[c0]), db = __ldg(&attD[c0 + 1]);
            as0 += acc[mi][ni][0] * sa + acc[mi][ni][1] * sb;
            ad0 += acc[mi][ni][0] * da + acc[mi][ni][1] * db;
            as1 += acc[mi][ni][2] * sa + acc[mi][ni][3] * sb;
            ad1 += acc[mi][ni][2] * da + acc[mi][ni][3] * db;
        }
        as0 += __shfl_xor_sync(0xffffffff, as0, 1); as0 += __shfl_xor_sync(0xffffffff, as0, 2);
        ad0 += __shfl_xor_sync(0xffffffff, ad0, 1); ad0 += __shfl_xor_sync(0xffffffff, ad0, 2);
        as1 += __shfl_xor_sync(0xffffffff, as1, 1); as1 += __shfl_xor_sync(0xffffffff, as1, 2);
        ad1 += __shfl_xor_sync(0xffffffff, ad1, 1); ad1 += __shfl_xor_sync(0xffffffff, ad1, 2);
        float e0 = __expf(lrelu(as0 + ad0));
        float e1 = __expf(lrelu(as1 + ad1));
        #pragma unroll
        for (int ni = 0; ni < 8; ni++) {
            int c0 = warpN * 64 + ni * 8 + 2 * tig;
            if (r0 < Nn) {
                *(__nv_bfloat162*)&g_h1b[r0 * F + c0] =
                    __float22bfloat162_rn(make_float2(acc[mi][ni][0], acc[mi][ni][1]));
                *(float2*)&g_out1[r0 * F + c0] =
                    make_float2(e0 * acc[mi][ni][0], e0 * acc[mi][ni][1]);
            }
            if (r1 < Nn) {
                *(__nv_bfloat162*)&g_h1b[r1 * F + c0] =
                    __float22bfloat162_rn(make_float2(acc[mi][ni][2], acc[mi][ni][3]));
                *(float2*)&g_out1[r1 * F + c0] =
                    make_float2(e1 * acc[mi][ni][2], e1 * acc[mi][ni][3]);
            }
        }
        if (tig == 0) {
            if (r0 < Nn) { g_asrc1[r0*2+warpN] = as0; g_adst1[r0*2+warpN] = ad0; g_den1[r0*2+warpN] = e0; }
            if (r1 < Nn) { g_asrc1[r1*2+warpN] = as1; g_adst1[r1*2+warpN] = ad1; g_den1[r1*2+warpN] = e1; }
        }
    }
}

// ======= esum: one thread per edge, both heads; den += exp(alpha) ============
template<int L>
__global__ __launch_bounds__(256)
void k_esum(const int* __restrict__ src, const int* __restrict__ dst) {
    int e = blockIdx.x * blockDim.x + threadIdx.x;
    if (e >= Ee) return;
    int s = __ldg(&src[e]), d = __ldg(&dst[e]);
    float2 a = *(const float2*)&P_asrc<L>()[s * 2];
    float2 b = *(const float2*)&P_adst<L>()[d * 2];
    red2(&P_den<L>()[d * 2], __expf(lrelu(a.x + b.x)), __expf(lrelu(a.y + b.y)));
}

// ======= msg1: warp/edge; per-lane exp (parallel, no shuffles); bf16 gather ==
__global__ __launch_bounds__(256)
void k_msg1(const int* __restrict__ src, const int* __restrict__ dst) {
    int warp = (blockIdx.x * blockDim.x + threadIdx.x) >> 5;
    int lane = threadIdx.x & 31;
    if (warp >= Ee) return;
    int s = __ldg(&src[warp]);
    int d = __ldg(&dst[warp]);
    int h = lane >> 4;                      // lanes 0..15 head0, 16..31 head1
    float w = __expf(lrelu(g_asrc1[s * 2 + h] + g_adst1[d * 2 + h]));
    uint2 p = *(const uint2*)((const char*)g_h1b + (size_t)s * 256 + lane * 8);
    float2 f0 = __bfloat1622float2(*(__nv_bfloat162*)&p.x);
    float2 f1 = __bfloat1622float2(*(__nv_bfloat162*)&p.y);
    red4(&g_out1[d * F + lane * 4], f0.x * w, f0.y * w, f1.x * w, f1.y * w);
}

// ----- BN stats over normalized out1; also den1 -> 1/den1 (fused rinv) -------
// Each block owns rows [i0, i0+64); inverts its own den entries (disjoint,
// race-free) and caches them in smem for the stats loop.
__global__ __launch_bounds__(128)
void k_stats() {
    __shared__ float sinv[128];             // 64 rows x 2 heads
    int c = threadIdx.x;                    // 128 threads, one per feature
    int i0 = blockIdx.x * 64;
    int head = c >> 6;
    int t = i0 * 2 + c;                     // den index covered by this thread
    if (t < 2 * Nn) {
        float inv = 1.0f / g_den1[t];
        g_den1[t] = inv;                    // write back for GEMM2's A-load
        sinv[c] = inv;
    }
    __syncthreads();
    float s = 0.f, q = 0.f;
    for (int r = 0; r < 64; r++) {
        int i = i0 + r;
        if (i >= Nn) break;
        float v = g_out1[i * F + c] * sinv[r * 2 + head];
        s += v; q += v * v;
    }
    atomicAdd(&g_bns[c], s);
    atomicAdd(&g_bnq[c], q);
}

// ================= GEMM2: h2 = BN(out1*invden) @ W2 (tf32) ===================
// BN finalize fused into prologue (each block recomputes scale/shift — trivial).
// block tile 128x80; warp tile 32(M) x 40(N); warpN == head
__global__ __launch_bounds__(256)
void k_gemm2(const float* __restrict__ W, const float* __restrict__ attS,
             const float* __restrict__ attD,
             const float* __restrict__ gamma, const float* __restrict__ beta) {
    __shared__ unsigned As[128][36];
    __shared__ unsigned Bs[32][88];
    __shared__ float sc[F], sh[F];
    int tid  = threadIdx.x;
    int lane = tid & 31, wid = tid >> 5;
    int warpM = wid & 3, warpN = wid >> 2;
    int g = lane >> 2, tig = lane & 3;
    int rowBase = blockIdx.x * 128;
    float acc[2][5][4] = {};

    if (tid < F) {                          // fused BN finalize
        float m = g_bns[tid] * (1.0f / (float)Nn);
        float v = g_bnq[tid] * (1.0f / (float)Nn) - m * m;
        float scv = __ldg(&gamma[tid]) * rsqrtf(v + EPS);
        sc[tid] = scv;
        sh[tid] = __ldg(&beta[tid]) - m * scv;
    }
    __syncthreads();

    for (int k0 = 0; k0 < F; k0 += 32) {
        #pragma unroll
        for (int l = 0; l < 4; l++) {               // A tile: normalize + BN at load
            int v = tid + l * 256;
            int r = v >> 3, kq = v & 7;
            int grow = rowBase + r;
            int kc = k0 + kq * 4;
            float4 xv = make_float4(0.f, 0.f, 0.f, 0.f);
            float inv = 0.f;
            if (grow < Nn) {
                xv  = *(const float4*)&g_out1[grow * F + kc];
                inv = g_den1[grow * 2 + (kc >= 64)];
            }
            As[r][kq*4+0] = f2tf32(xv.x * inv * sc[kc+0] + sh[kc+0]);
            As[r][kq*4+1] = f2tf32(xv.y * inv * sc[kc+1] + sh[kc+1]);
            As[r][kq*4+2] = f2tf32(xv.z * inv * sc[kc+2] + sh[kc+2]);
            As[r][kq*4+3] = f2tf32(xv.w * inv * sc[kc+3] + sh[kc+3]);
        }
        #pragma unroll
        for (int l = 0; l < 3; l++) {               // B tile 32x80 = 640 float4
            int v = tid + l * 256;
            if (v < 640) {
                int kk = v / 20, nq = v % 20;
                float4 wv = *(const float4*)&W[(k0 + kk) * C2T + nq * 4];
                Bs[kk][nq*4+0] = f2tf32(wv.x); Bs[kk][nq*4+1] = f2tf32(wv.y);
                Bs[kk][nq*4+2] = f2tf32(wv.z); Bs[kk][nq*4+3] = f2tf32(wv.w);
            }
        }
        __syncthreads();
        #pragma unroll
        for (int ks = 0; ks < 4; ks++) {
            unsigned a[2][4];
            #pragma unroll
            for (int mi = 0; mi < 2; mi++) {
                int r = warpM * 32 + mi * 16 + g;
                a[mi][0] = As[r    ][ks*8 + tig];
                a[mi][1] = As[r + 8][ks*8 + tig];
                a[mi][2] = As[r    ][ks*8 + tig + 4];
                a[mi][3] = As[r + 8][ks*8 + tig + 4];
            }
            #pragma unroll
            for (int ni = 0; ni < 5; ni++) {
                unsigned b[2];
                int c = warpN * 40 + ni * 8 + g;
                b[0] = Bs[ks*8 + tig    ][c];
                b[1] = Bs[ks*8 + tig + 4][c];
                mma_tf32(acc[0][ni], a[0], b);
                mma_tf32(acc[1][ni], a[1], b);
            }
        }
        __syncthreads();
    }

    #pragma unroll
    for (int mi = 0; mi < 2; mi++) {
        int r0 = rowBase + warpM * 32 + mi * 16 + g;
        int r1 = r0 + 8;
        float as0 = 0.f, ad0 = 0.f, as1 = 0.f, ad1 = 0.f;
        #pragma unroll
        for (int ni = 0; ni < 5; ni++) {
            int c0 = warpN * 40 + ni * 8 + 2 * tig;
            float sa = __ldg(&attS[c0]), sb = __ldg(&attS[c0 + 1]);
            float da = __ldg(&attD[c0]), db = __ldg(&attD[c0 + 1]);
            as0 += acc[mi][ni][0] * sa + acc[mi][ni][1] * sb;
            ad0 += acc[mi][ni][0] * da + acc[mi][ni][1] * db;
            as1 += acc[mi][ni][2] * sa + acc[mi][ni][3] * sb;
            ad1 += acc[mi][ni][2] * da + acc[mi][ni][3] * db;
        }
        as0 += __shfl_xor_sync(0xffffffff, as0, 1); as0 += __shfl_xor_sync(0xffffffff, as0, 2);
        ad0 += __shfl_xor_sync(0xffffffff, ad0, 1); ad0 += __shfl_xor_sync(0xffffffff, ad0, 2);
        as1 += __shfl_xor_sync(0xffffffff, as1, 1); as1 += __shfl_xor_sync(0xffffffff, as1, 2);
        ad1 += __shfl_xor_sync(0xffffffff, ad1, 1); ad1 += __shfl_xor_sync(0xffffffff, ad1, 2);
        float e0 = __expf(lrelu(as0 + ad0));
        float e1 = __expf(lrelu(as1 + ad1));
        #pragma unroll
        for (int ni = 0; ni < 5; ni++) {
            int c0 = warpN * 40 + ni * 8 + 2 * tig;
            if (r0 < Nn) {
                *(__nv_bfloat162*)&g_h2b[r0 * C2T + c0] =
                    __float22bfloat162_rn(make_float2(acc[mi][ni][0], acc[mi][ni][1]));
                *(float2*)&g_out2[r0 * C2T + c0] =
                    make_float2(e0 * acc[mi][ni][0], e0 * acc[mi][ni][1]);
            }
            if (r1 < Nn) {
                *(__nv_bfloat162*)&g_h2b[r1 * C2T + c0] =
                    __float22bfloat162_rn(make_float2(acc[mi][ni][2], acc[mi][ni][3]));
                *(float2*)&g_out2[r1 * C2T + c0] =
                    make_float2(e1 * acc[mi][ni][2], e1 * acc[mi][ni][3]);
            }
        }
        if (tig == 0) {
            if (r0 < Nn) { g_asrc2[r0*2+warpN] = as0; g_adst2[r0*2+warpN] = ad0; g_den2[r0*2+warpN] = e0; }
            if (r1 < Nn) { g_asrc2[r1*2+warpN] = as1; g_adst2[r1*2+warpN] = ad1; g_den2[r1*2+warpN] = e1; }
        }
    }
}

// ======= msg2: warp/edge (20 active lanes); per-lane exp; bf16 gather ========
__global__ __launch_bounds__(256)
void k_msg2(const int* __restrict__ src, const int* __restrict__ dst) {
    int warp = (blockIdx.x * blockDim.x + threadIdx.x) >> 5;
    int lane = threadIdx.x & 31;
    if (warp >= Ee || lane >= 20) return;
    int s = __ldg(&src[warp]);
    int d = __ldg(&dst[warp]);
    int h = lane >= 10;
    int q = lane - h * 10;
    float w = __expf(lrelu(g_asrc2[s * 2 + h] + g_adst2[d * 2 + h]));
    uint2 p = *(const uint2*)((const char*)g_h2b + (size_t)s * 160 + h * 80 + q * 8);
    float2 f0 = __bfloat1622float2(*(__nv_bfloat162*)&p.x);
    float2 f1 = __bfloat1622float2(*(__nv_bfloat162*)&p.y);
    red4(&g_out2[d * C2T + h * 40 + q * 4], f0.x * w, f0.y * w, f1.x * w, f1.y * w);
}

// ------- final: normalize + head mean + bias + log_softmax -------------------
__global__ __launch_bounds__(256)
void k_final2(const float* __restrict__ b2, float* __restrict__ out) {
    int i = (blockIdx.x * blockDim.x + threadIdx.x) >> 5;
    int lane = threadIdx.x & 31;
    if (i >= Nn) return;
    float2 dn = *(const float2*)&g_den2[i * 2];
    float inv0 = 0.5f / dn.x;
    float inv1 = 0.5f / dn.y;
    const float* o = &g_out2[i * C2T];

    int c = lane;                            // classes 0..31
    float va = o[c] * inv0 + o[40 + c] * inv1 + __ldg(&b2[c]);
    float vb = -1e30f;
    if (lane < 8) {
        int cb = lane + 32;
        vb = o[cb] * inv0 + o[40 + cb] * inv1 + __ldg(&b2[cb]);
    }
    float m = fmaxf(va, vb);
    #pragma unroll
    for (int off = 16; off; off >>= 1) m = fmaxf(m, __shfl_xor_sync(0xffffffff, m, off));
    float s = __expf(va - m) + (lane < 8 ? __expf(vb - m) : 0.f);
    #pragma unroll
    for (int off = 16; off; off >>= 1) s += __shfl_xor_sync(0xffffffff, s, off);
    float lg = m + __logf(s);
    out[i * NCls + lane] = va - lg;
    if (lane < 8) out[i * NCls + 32 + lane] = vb - lg;
}

// ---------------- launch -----------------------------------------------------
extern "C" void kernel_launch(void* const* d_in, const int* in_sizes, int n_in,
                              void* d_out, int out_size) {
    const float* x     = (const float*)d_in[0];
    const int*   ei    = (const int*)  d_in[1];
    const float* W1    = (const float*)d_in[2];
    const float* as1   = (const float*)d_in[3];
    const float* ad1   = (const float*)d_in[4];
    // d_in[5] = b1 (cancels inside BatchNorm — unused)
    const float* gamma = (const float*)d_in[6];
    const float* beta  = (const float*)d_in[7];
    const float* W2    = (const float*)d_in[8];
    const float* as2   = (const float*)d_in[9];
    const float* ad2   = (const float*)d_in[10];
    const float* b2    = (const float*)d_in[11];
    float* out = (float*)d_out;

    const int* src = ei;
    const int* dst = ei + Ee;

    const int TB = 256;
    int gG  = (Nn + 127) / 128;
    int gE  = (Ee + TB - 1) / TB;            // thread per edge
    int gEw = (Ee * 32 + TB - 1) / TB;       // warp per edge

    // ---- layer 1 ----
    k_gemm1<<<gG, TB>>>(x, W1, as1, ad1);
    k_esum<1><<<gE, TB>>>(src, dst);
    k_msg1<<<gEw, TB>>>(src, dst);
    k_stats<<<(Nn + 63) / 64, 128>>>();      // fused: rinv(den1) + BN stats
    // ---- layer 2 ----
    k_gemm2<<<gG, TB>>>(W2, as2, ad2, gamma, beta);
    k_esum<2><<<gE, TB>>>(src, dst);
    k_msg2<<<gEw, TB>>>(src, dst);
    k_final2<<<(Nn * 32 + TB - 1) / TB, TB>>>(b2, out);
}